// round 16
// baseline (speedup 1.0000x reference)
#include <cuda_runtime.h>
#include <cstdint>

#define DIM    1024
#define KC     32
#define MROWS  176
#define TPB    352
#define KCH    32
#define NCH    (DIM / KCH)        // 32 chunks
// X stage: fp32, row pitch 160B -> conflict-free LDS.64 fragments
#define PXB    160
#define XST_B  (MROWS * PXB)              // 28160 B
#define CP_REL XST_B                      // packed C region within stage
#define CP_B   4096                       // 256 records * 16B
#define STAGE_B (XST_B + CP_B)            // 32256 B
#define NSTG   3
#define SSQ_REL (NSTG * STAGE_B)          // 96768
#define SMEM_B  (SSQ_REL + KC * 4)        // 96896 B

// ---- device scratch ----
// g_Cp[(kt*8 + nt*2 + s)*32 + lane] = {bh0, bh1, bl0, bl1}
__device__ __align__(16) uint4 g_Cp[NCH * 8 * 32];   // 128 KB
__device__ float g_sqPart[NCH * KC];                 // per-chunk ||mu||^2 partials
__device__ unsigned int g_ctr;                       // pack completion counter

static __device__ __forceinline__ uint32_t s2u(const void* p) {
    uint32_t a;
    asm("{ .reg .u64 t; cvta.to.shared.u64 t, %1; cvt.u32.u64 %0, t; }" : "=r"(a) : "l"(p));
    return a;
}
static __device__ __forceinline__ uint64_t g2u(const void* p) {
    uint64_t a;
    asm("cvta.to.global.u64 %0, %1;" : "=l"(a) : "l"(p));
    return a;
}

// split fp32 pair into bf16x2 hi + bf16x2 lo (RN both stages); low half = first arg
static __device__ __forceinline__ void split2(float x0, float x1,
                                              uint32_t& hi2, uint32_t& lo2) {
    asm("cvt.rn.bf16x2.f32 %0, %1, %2;" : "=r"(hi2) : "f"(x1), "f"(x0));
    float h0 = __uint_as_float(hi2 << 16);
    float h1 = __uint_as_float(hi2 & 0xFFFF0000u);
    float l0 = x0 - h0, l1 = x1 - h1;
    asm("cvt.rn.bf16x2.f32 %0, %1, %2;" : "=r"(lo2) : "f"(l1), "f"(l0));
}

static __device__ __forceinline__ void mma_bf16(float* c, const uint32_t* a,
                                                uint32_t b0, uint32_t b1) {
    asm volatile(
        "mma.sync.aligned.m16n8k16.row.col.f32.bf16.bf16.f32 "
        "{%0,%1,%2,%3}, {%4,%5,%6,%7}, {%8,%9}, {%0,%1,%2,%3};"
        : "+f"(c[0]), "+f"(c[1]), "+f"(c[2]), "+f"(c[3])
        : "r"(a[0]), "r"(a[1]), "r"(a[2]), "r"(a[3]), "r"(b0), "r"(b1));
}

#define CPA16(dst, src) asm volatile("cp.async.cg.shared.global [%0], [%1], 16;" :: "r"(dst), "l"(src) : "memory")
#define CPA_COMMIT()    asm volatile("cp.async.commit_group;" ::: "memory")
#define LDS64F(vx, vy, a) asm volatile("ld.shared.v2.f32 {%0,%1},[%2];" : "=f"(vx), "=f"(vy) : "r"(a))
#define LDS128U(r0, r1, r2, r3, a) \
    asm volatile("ld.shared.v4.b32 {%0,%1,%2,%3},[%4];" \
                 : "=r"(r0), "=r"(r1), "=r"(r2), "=r"(r3) : "r"(a))

__global__ __launch_bounds__(TPB, 2)
void nkm_mma(const float* __restrict__ X, const float* __restrict__ C,
             float* __restrict__ out, int N) {
    extern __shared__ char smem[];
    const uint32_t sb = s2u(smem);
    float* sSqS = reinterpret_cast<float*>(smem + SSQ_REL);

    const int tid  = threadIdx.x;
    const int w    = tid >> 5;        // 0..10, warp owns rows 16w..16w+15
    const int lane = tid & 31;
    const int g    = lane >> 2;
    const int ql   = lane & 3;
    const int blockBase = blockIdx.x * MROWS;

    // ---- cp.async source/dest maps ----
    // X: 176 rows x 8 float4 = 1408 transfers = 352 threads x 4
    const uint64_t Xg = g2u(X);
    uint64_t xsrc[4];
    uint32_t xdst[4];
#pragma unroll
    for (int i = 0; i < 4; i++) {
        int idx = tid + TPB * i;
        int r = idx >> 3, f = idx & 7;
        int gr = blockBase + r;
        if (gr >= N) gr = N - 1;      // clamp; outputs guarded
        xsrc[i] = Xg + ((uint64_t)gr * DIM + 4 * (uint64_t)f) * 4ull;
        xdst[i] = (uint32_t)(PXB * r + 16 * f);
    }
    // C records: 256 per chunk; threads 0..255 move one each
    const uint64_t csrc = g2u(g_Cp) + (uint64_t)tid * 16ull;
    const uint32_t cdst = CP_REL + (uint32_t)tid * 16u;
    const bool doC = (tid < 256);

#define ISSUE_X(ktv, stg)                                                       \
    do {                                                                        \
        uint32_t _bs = sb + (uint32_t)(stg) * STAGE_B;                          \
        uint64_t _ko = (uint64_t)(ktv) * (KCH * 4);                             \
        CPA16(_bs + xdst[0], xsrc[0] + _ko);                                    \
        CPA16(_bs + xdst[1], xsrc[1] + _ko);                                    \
        CPA16(_bs + xdst[2], xsrc[2] + _ko);                                    \
        CPA16(_bs + xdst[3], xsrc[3] + _ko);                                    \
        CPA_COMMIT();                                                           \
    } while (0)
#define ISSUE_C(ktv, stg)                                                       \
    do {                                                                        \
        if (doC) CPA16(sb + (uint32_t)(stg) * STAGE_B + cdst,                   \
                       csrc + (uint64_t)(ktv) * CP_B);                          \
        CPA_COMMIT();                                                           \
    } while (0)
#define ISSUE_XC(ktv, stg)                                                      \
    do {                                                                        \
        uint32_t _bs = sb + (uint32_t)(stg) * STAGE_B;                          \
        uint64_t _ko = (uint64_t)(ktv) * (KCH * 4);                             \
        CPA16(_bs + xdst[0], xsrc[0] + _ko);                                    \
        CPA16(_bs + xdst[1], xsrc[1] + _ko);                                    \
        CPA16(_bs + xdst[2], xsrc[2] + _ko);                                    \
        CPA16(_bs + xdst[3], xsrc[3] + _ko);                                    \
        if (doC) CPA16(_bs + cdst, csrc + (uint64_t)(ktv) * CP_B);              \
        CPA_COMMIT();                                                           \
    } while (0)

    // ---- start X streaming immediately (overlaps with C packing) ----
    ISSUE_X(0, 0);                    // group 0
    ISSUE_X(1, 1);                    // group 1

    // ---- producer: first NCH CTAs each pack one C chunk ----
    if (blockIdx.x < NCH) {
        const int kt = blockIdx.x;
        float* scr = reinterpret_cast<float*>(smem + 2 * STAGE_B + CP_REL); // stage2 C region, 4KB
        if (doC) {   // load 32x32 C chunk (coalesced): 256 float4
            const float4* C4g = reinterpret_cast<const float4*>(C);
            float4 v = C4g[(tid >> 3) * (DIM / 4) + kt * 8 + (tid & 7)];
            *reinterpret_cast<float4*>(scr + (tid >> 3) * 32 + (tid & 7) * 4) = v;
        }
        __syncthreads();
        if (doC) {
            const int l = tid & 31, s5 = (tid >> 5) & 1, nt = tid >> 6;
            const int gg = l >> 2, qq = l & 3;
            const int row = 8 * nt + gg;
            const int k0 = 16 * s5 + 2 * qq;
            float a0 = scr[row * 32 + k0],     a1 = scr[row * 32 + k0 + 1];
            float b0 = scr[row * 32 + k0 + 8], b1 = scr[row * 32 + k0 + 9];
            uint32_t w0, w1, w2, w3;
            split2(a0, a1, w0, w2);
            split2(b0, b1, w1, w3);
            g_Cp[(kt * 8 + nt * 2 + s5) * 32 + l] = make_uint4(w0, w1, w2, w3);
        }
        if (tid < KC) {
            float sq = 0.0f;
#pragma unroll
            for (int i = 0; i < 32; i++) { float c = scr[tid * 32 + i]; sq += c * c; }
            g_sqPart[kt * KC + tid] = sq;
        }
        __syncthreads();
        if (tid == 0) { __threadfence(); atomicAdd(&g_ctr, 1u); }
    }

    // ---- consumer spin: wait until all NCH chunks are packed ----
    if (tid == 0) {
        unsigned int v;
        do {
            asm volatile("ld.global.acquire.gpu.u32 %0, [%1];" : "=r"(v) : "l"(&g_ctr));
        } while (v < (unsigned)NCH);
    }
    __syncthreads();

    // sSq = sum of per-chunk partials
    if (tid < KC) {
        float s = 0.0f;
#pragma unroll
        for (int kt = 0; kt < NCH; kt++) s += g_sqPart[kt * KC + tid];
        sSqS[tid] = s;
    }

    ISSUE_C(0, 0);                    // group 2
    ISSUE_C(1, 1);                    // group 3

    float acc[4][4];
#pragma unroll
    for (int nt = 0; nt < 4; nt++)
#pragma unroll
        for (int i = 0; i < 4; i++) acc[nt][i] = 0.0f;

    const uint32_t aRow = (uint32_t)(PXB * (16 * w + g));   // X row byte offset
    const uint32_t bIdx = (uint32_t)(lane * 16);            // packed C lane offset

    int rd = 0;                       // read stage = kt % 3
#pragma unroll 1
    for (int kt = 0; kt < NCH; kt++) {
        if (kt + 1 < NCH) {
            asm volatile("cp.async.wait_group 1;" ::: "memory");
        } else {
            asm volatile("cp.async.wait_group 0;" ::: "memory");
        }
        __syncthreads();              // stage kt visible; stage (kt-1)%3 freed

        if (kt + 2 < NCH) {
            int ib = rd + 2; if (ib >= NSTG) ib -= NSTG;
            ISSUE_XC(kt + 2, ib);
        }

        const uint32_t bb = sb + (uint32_t)rd * STAGE_B;
#pragma unroll
        for (int s = 0; s < 2; s++) {
            // A fragments: fp32 LDS.64 + in-register split
            const uint32_t aa = bb + aRow + 8 * ql + 64 * s;
            float2 f0, f1, f2, f3;
            LDS64F(f0.x, f0.y, aa);                 // row g,   k 2ql..
            LDS64F(f1.x, f1.y, aa + 8 * PXB);       // row g+8
            LDS64F(f2.x, f2.y, aa + 32);            // row g,   k+8
            LDS64F(f3.x, f3.y, aa + 8 * PXB + 32);  // row g+8, k+8
            uint32_t ah[4], al[4];
            split2(f0.x, f0.y, ah[0], al[0]);
            split2(f1.x, f1.y, ah[1], al[1]);
            split2(f2.x, f2.y, ah[2], al[2]);
            split2(f3.x, f3.y, ah[3], al[3]);

#pragma unroll
            for (int nt = 0; nt < 4; nt++) {
                uint32_t bh0, bh1, bl0, bl1;
                LDS128U(bh0, bh1, bl0, bl1,
                        bb + CP_REL + (uint32_t)((nt * 2 + s) * 512) + bIdx);
                mma_bf16(acc[nt], ah, bh0, bh1);   // hi*hi
                mma_bf16(acc[nt], ah, bl0, bl1);   // hi*lo
                mma_bf16(acc[nt], al, bh0, bh1);   // lo*hi
            }
        }
        if (++rd == NSTG) rd = 0;
    }

    // ---- epilogue: s = 2*dot - sq ; top2 per row; merge across quad ----
    const float NEG_INF = -__int_as_float(0x7f800000);
    float m1[2] = {NEG_INF, NEG_INF};
    float m2[2] = {NEG_INF, NEG_INF};
#pragma unroll
    for (int nt = 0; nt < 4; nt++) {
        const int c0 = 8 * nt + ql * 2;
        const float q0 = sSqS[c0], q1 = sSqS[c0 + 1];
        float s;
        s = 2.0f * acc[nt][0] - q0;
        if (s > m1[0]) { m2[0] = m1[0]; m1[0] = s; } else if (s > m2[0]) m2[0] = s;
        s = 2.0f * acc[nt][1] - q1;
        if (s > m1[0]) { m2[0] = m1[0]; m1[0] = s; } else if (s > m2[0]) m2[0] = s;
        s = 2.0f * acc[nt][2] - q0;
        if (s > m1[1]) { m2[1] = m1[1]; m1[1] = s; } else if (s > m2[1]) m2[1] = s;
        s = 2.0f * acc[nt][3] - q1;
        if (s > m1[1]) { m2[1] = m1[1]; m1[1] = s; } else if (s > m2[1]) m2[1] = s;
    }
#pragma unroll
    for (int delta = 1; delta <= 2; delta <<= 1) {
#pragma unroll
        for (int r = 0; r < 2; r++) {
            float om1 = __shfl_xor_sync(0xffffffffu, m1[r], delta);
            float om2 = __shfl_xor_sync(0xffffffffu, m2[r], delta);
            float nm1 = fmaxf(m1[r], om1);
            float nm2 = fmaxf(fminf(m1[r], om1), fmaxf(m2[r], om2));
            m1[r] = nm1;
            m2[r] = nm2;
        }
    }
    if (ql == 0) {
        int r0 = blockBase + 16 * w + g;
        if (r0 < N)     out[r0]     = m1[0] - m2[0];
        if (r0 + 8 < N) out[r0 + 8] = m1[1] - m2[1];
    }
#undef ISSUE_X
#undef ISSUE_C
#undef ISSUE_XC
}

extern "C" void kernel_launch(void* const* d_in, const int* in_sizes, int n_in,
                              void* d_out, int out_size) {
    const float* X = (const float*)d_in[0];   // [N, 1024]
    const float* C = (const float*)d_in[1];   // [32, 1024]
    float* out = (float*)d_out;               // [N]
    int N = in_sizes[0] / DIM;
    int nb = (N + MROWS - 1) / MROWS;

    cudaFuncSetAttribute(nkm_mma, cudaFuncAttributeMaxDynamicSharedMemorySize, SMEM_B);
    nkm_mma<<<nb, TPB, SMEM_B>>>(X, C, out, N);
}

// round 17
// speedup vs baseline: 1.0322x; 1.0322x over previous
#include <cuda_runtime.h>
#include <cstdint>

#define DIM    1024
#define KC     32
#define MROWS  128
#define TPB    256
#define KCH    32
#define NCH    (DIM / KCH)        // 32 chunks
// X stage: fp32, row pitch 160B -> conflict-free LDS.64 fragments
#define PXB    160
#define XST_B  (MROWS * PXB)              // 20480 B
#define CP_REL XST_B                      // packed C region within stage
#define CP_B   4096                       // 256 threads * 16B
#define STAGE_B (XST_B + CP_B)            // 24576 B
#define NSTG   3
#define SSQ_REL (NSTG * STAGE_B)          // 73728
#define SMEM_B  (SSQ_REL + KC * 4)        // 73856 B

// ---- device scratch ----
// g_Cp[(kt*8 + nt*2 + s)*32 + lane] = {bh0, bh1, bl0, bl1}
__device__ __align__(16) uint4 g_Cp[NCH * 8 * 32];   // 128 KB
__device__ float g_sqPart[NCH * KC];                 // per-chunk ||mu||^2 partials
__device__ unsigned int g_ctr;                       // pack completion counter

static __device__ __forceinline__ uint32_t s2u(const void* p) {
    uint32_t a;
    asm("{ .reg .u64 t; cvta.to.shared.u64 t, %1; cvt.u32.u64 %0, t; }" : "=r"(a) : "l"(p));
    return a;
}
static __device__ __forceinline__ uint64_t g2u(const void* p) {
    uint64_t a;
    asm("cvta.to.global.u64 %0, %1;" : "=l"(a) : "l"(p));
    return a;
}

// split fp32 pair into bf16x2 hi + bf16x2 lo (RN both stages); low half = first arg
static __device__ __forceinline__ void split2(float x0, float x1,
                                              uint32_t& hi2, uint32_t& lo2) {
    asm("cvt.rn.bf16x2.f32 %0, %1, %2;" : "=r"(hi2) : "f"(x1), "f"(x0));
    float h0 = __uint_as_float(hi2 << 16);
    float h1 = __uint_as_float(hi2 & 0xFFFF0000u);
    float l0 = x0 - h0, l1 = x1 - h1;
    asm("cvt.rn.bf16x2.f32 %0, %1, %2;" : "=r"(lo2) : "f"(l1), "f"(l0));
}

static __device__ __forceinline__ void mma_bf16(float* c, const uint32_t* a,
                                                uint32_t b0, uint32_t b1) {
    asm volatile(
        "mma.sync.aligned.m16n8k16.row.col.f32.bf16.bf16.f32 "
        "{%0,%1,%2,%3}, {%4,%5,%6,%7}, {%8,%9}, {%0,%1,%2,%3};"
        : "+f"(c[0]), "+f"(c[1]), "+f"(c[2]), "+f"(c[3])
        : "r"(a[0]), "r"(a[1]), "r"(a[2]), "r"(a[3]), "r"(b0), "r"(b1));
}

#define CPA16(dst, src) asm volatile("cp.async.cg.shared.global [%0], [%1], 16;" :: "r"(dst), "l"(src) : "memory")
#define CPA_COMMIT()    asm volatile("cp.async.commit_group;" ::: "memory")
#define LDS64F(vx, vy, a) asm volatile("ld.shared.v2.f32 {%0,%1},[%2];" : "=f"(vx), "=f"(vy) : "r"(a))
#define LDS128U(r0, r1, r2, r3, a) \
    asm volatile("ld.shared.v4.b32 {%0,%1,%2,%3},[%4];" \
                 : "=r"(r0), "=r"(r1), "=r"(r2), "=r"(r3) : "r"(a))

__global__ __launch_bounds__(TPB, 3)
void nkm_mma(const float* __restrict__ X, const float* __restrict__ C,
             float* __restrict__ out, int N) {
    extern __shared__ char smem[];
    const uint32_t sb = s2u(smem);
    float* sSqS = reinterpret_cast<float*>(smem + SSQ_REL);

    const int tid  = threadIdx.x;
    const int w    = tid >> 5;        // 0..7, warp owns rows 16w..16w+15
    const int lane = tid & 31;
    const int g    = lane >> 2;
    const int ql   = lane & 3;
    const int blockBase = blockIdx.x * MROWS;

    // ---- cp.async source/dest maps ----
    const uint64_t Xg = g2u(X);
    uint64_t xsrc[4];
    uint32_t xdst[4];
#pragma unroll
    for (int i = 0; i < 4; i++) {
        int idx = tid + 256 * i;
        int r = idx >> 3, f = idx & 7;
        int gr = blockBase + r;
        if (gr >= N) gr = N - 1;      // clamp; outputs guarded
        xsrc[i] = Xg + ((uint64_t)gr * DIM + 4 * (uint64_t)f) * 4ull;
        xdst[i] = (uint32_t)(PXB * r + 16 * f);
    }
    const uint64_t csrc = g2u(g_Cp) + (uint64_t)tid * 16ull;
    const uint32_t cdst = CP_REL + (uint32_t)tid * 16u;

#define ISSUE_X(ktv, stg)                                                       \
    do {                                                                        \
        uint32_t _bs = sb + (uint32_t)(stg) * STAGE_B;                          \
        uint64_t _ko = (uint64_t)(ktv) * (KCH * 4);                             \
        CPA16(_bs + xdst[0], xsrc[0] + _ko);                                    \
        CPA16(_bs + xdst[1], xsrc[1] + _ko);                                    \
        CPA16(_bs + xdst[2], xsrc[2] + _ko);                                    \
        CPA16(_bs + xdst[3], xsrc[3] + _ko);                                    \
        CPA_COMMIT();                                                           \
    } while (0)
#define ISSUE_C(ktv, stg)                                                       \
    do {                                                                        \
        CPA16(sb + (uint32_t)(stg) * STAGE_B + cdst, csrc + (uint64_t)(ktv) * CP_B); \
        CPA_COMMIT();                                                           \
    } while (0)
#define ISSUE_XC(ktv, stg)                                                      \
    do {                                                                        \
        uint32_t _bs = sb + (uint32_t)(stg) * STAGE_B;                          \
        uint64_t _ko = (uint64_t)(ktv) * (KCH * 4);                             \
        CPA16(_bs + xdst[0], xsrc[0] + _ko);                                    \
        CPA16(_bs + xdst[1], xsrc[1] + _ko);                                    \
        CPA16(_bs + xdst[2], xsrc[2] + _ko);                                    \
        CPA16(_bs + xdst[3], xsrc[3] + _ko);                                    \
        CPA16(_bs + cdst, csrc + (uint64_t)(ktv) * CP_B);                       \
        CPA_COMMIT();                                                           \
    } while (0)

    // ---- start X streaming immediately (overlaps with C packing) ----
    ISSUE_X(0, 0);                    // group 0
    ISSUE_X(1, 1);                    // group 1

    // ---- producer: first NCH CTAs each pack one C chunk ----
    if (blockIdx.x < NCH) {
        const int kt = blockIdx.x;
        float* scr = reinterpret_cast<float*>(smem + 2 * STAGE_B + CP_REL); // stage2 C region, 4KB
        {
            const float4* C4g = reinterpret_cast<const float4*>(C);
            float4 v = C4g[(tid >> 3) * (DIM / 4) + kt * 8 + (tid & 7)];
            *reinterpret_cast<float4*>(scr + (tid >> 3) * 32 + (tid & 7) * 4) = v;
        }
        __syncthreads();
        {
            const int l = tid & 31, s5 = (tid >> 5) & 1, nt = tid >> 6;
            const int gg = l >> 2, qq = l & 3;
            const int row = 8 * nt + gg;
            const int k0 = 16 * s5 + 2 * qq;
            float a0 = scr[row * 32 + k0],     a1 = scr[row * 32 + k0 + 1];
            float b0 = scr[row * 32 + k0 + 8], b1 = scr[row * 32 + k0 + 9];
            uint32_t w0, w1, w2, w3;
            split2(a0, a1, w0, w2);
            split2(b0, b1, w1, w3);
            g_Cp[(kt * 8 + nt * 2 + s5) * 32 + l] = make_uint4(w0, w1, w2, w3);
            if (tid < KC) {
                float sq = 0.0f;
#pragma unroll
                for (int i = 0; i < 32; i++) { float c = scr[tid * 32 + i]; sq += c * c; }
                g_sqPart[kt * KC + tid] = sq;
            }
        }
        __syncthreads();
        if (tid == 0) { __threadfence(); atomicAdd(&g_ctr, 1u); }
    }

    // ---- consumer spin: wait until all NCH chunks are packed ----
    if (tid == 0) {
        unsigned int v;
        do {
            asm volatile("ld.global.acquire.gpu.u32 %0, [%1];" : "=r"(v) : "l"(&g_ctr));
        } while (v < (unsigned)NCH);
    }
    __syncthreads();

    // sSq = sum of per-chunk partials
    if (tid < KC) {
        float s = 0.0f;
#pragma unroll
        for (int kt = 0; kt < NCH; kt++) s += g_sqPart[kt * KC + tid];
        sSqS[tid] = s;
    }

    ISSUE_C(0, 0);                    // group 2
    ISSUE_C(1, 1);                    // group 3

    float acc[4][4];
#pragma unroll
    for (int nt = 0; nt < 4; nt++)
#pragma unroll
        for (int i = 0; i < 4; i++) acc[nt][i] = 0.0f;

    const uint32_t aRow = (uint32_t)(PXB * (16 * w + g));   // X row byte offset
    const uint32_t bIdx = (uint32_t)(lane * 16);            // packed C lane offset

    int rd = 0;                       // read stage = kt % 3
#pragma unroll 1
    for (int kt = 0; kt < NCH; kt++) {
        if (kt + 1 < NCH) {
            asm volatile("cp.async.wait_group 1;" ::: "memory");
        } else {
            asm volatile("cp.async.wait_group 0;" ::: "memory");
        }
        __syncthreads();              // stage kt visible; stage (kt-1)%3 freed

        if (kt + 2 < NCH) {
            int ib = rd + 2; if (ib >= NSTG) ib -= NSTG;
            ISSUE_XC(kt + 2, ib);
        }

        const uint32_t bb = sb + (uint32_t)rd * STAGE_B;
#pragma unroll
        for (int s = 0; s < 2; s++) {
            // A fragments: fp32 LDS.64 + in-register split
            const uint32_t aa = bb + aRow + 8 * ql + 64 * s;
            float2 f0, f1, f2, f3;
            LDS64F(f0.x, f0.y, aa);                 // row g,   k 2ql..
            LDS64F(f1.x, f1.y, aa + 8 * PXB);       // row g+8
            LDS64F(f2.x, f2.y, aa + 32);            // row g,   k+8
            LDS64F(f3.x, f3.y, aa + 8 * PXB + 32);  // row g+8, k+8
            uint32_t ah[4], al[4];
            split2(f0.x, f0.y, ah[0], al[0]);
            split2(f1.x, f1.y, ah[1], al[1]);
            split2(f2.x, f2.y, ah[2], al[2]);
            split2(f3.x, f3.y, ah[3], al[3]);

#pragma unroll
            for (int nt = 0; nt < 4; nt++) {
                uint32_t bh0, bh1, bl0, bl1;
                LDS128U(bh0, bh1, bl0, bl1,
                        bb + CP_REL + (uint32_t)((nt * 2 + s) * 512) + bIdx);
                mma_bf16(acc[nt], ah, bh0, bh1);   // hi*hi
                mma_bf16(acc[nt], ah, bl0, bl1);   // hi*lo
                mma_bf16(acc[nt], al, bh0, bh1);   // lo*hi
            }
        }
        if (++rd == NSTG) rd = 0;
    }

    // ---- epilogue: s = 2*dot - sq ; top2 per row; merge across quad ----
    const float NEG_INF = -__int_as_float(0x7f800000);
    float m1[2] = {NEG_INF, NEG_INF};
    float m2[2] = {NEG_INF, NEG_INF};
#pragma unroll
    for (int nt = 0; nt < 4; nt++) {
        const int c0 = 8 * nt + ql * 2;
        const float q0 = sSqS[c0], q1 = sSqS[c0 + 1];
        float s;
        s = 2.0f * acc[nt][0] - q0;
        if (s > m1[0]) { m2[0] = m1[0]; m1[0] = s; } else if (s > m2[0]) m2[0] = s;
        s = 2.0f * acc[nt][1] - q1;
        if (s > m1[0]) { m2[0] = m1[0]; m1[0] = s; } else if (s > m2[0]) m2[0] = s;
        s = 2.0f * acc[nt][2] - q0;
        if (s > m1[1]) { m2[1] = m1[1]; m1[1] = s; } else if (s > m2[1]) m2[1] = s;
        s = 2.0f * acc[nt][3] - q1;
        if (s > m1[1]) { m2[1] = m1[1]; m1[1] = s; } else if (s > m2[1]) m2[1] = s;
    }
#pragma unroll
    for (int delta = 1; delta <= 2; delta <<= 1) {
#pragma unroll
        for (int r = 0; r < 2; r++) {
            float om1 = __shfl_xor_sync(0xffffffffu, m1[r], delta);
            float om2 = __shfl_xor_sync(0xffffffffu, m2[r], delta);
            float nm1 = fmaxf(m1[r], om1);
            float nm2 = fmaxf(fminf(m1[r], om1), fmaxf(m2[r], om2));
            m1[r] = nm1;
            m2[r] = nm2;
        }
    }
    if (ql == 0) {
        int r0 = blockBase + 16 * w + g;
        if (r0 < N)     out[r0]     = m1[0] - m2[0];
        if (r0 + 8 < N) out[r0 + 8] = m1[1] - m2[1];
    }
#undef ISSUE_X
#undef ISSUE_C
#undef ISSUE_XC
}

extern "C" void kernel_launch(void* const* d_in, const int* in_sizes, int n_in,
                              void* d_out, int out_size) {
    const float* X = (const float*)d_in[0];   // [N, 1024]
    const float* C = (const float*)d_in[1];   // [32, 1024]
    float* out = (float*)d_out;               // [N]
    int N = in_sizes[0] / DIM;
    int nb = (N + MROWS - 1) / MROWS;

    cudaFuncSetAttribute(nkm_mma, cudaFuncAttributeMaxDynamicSharedMemorySize, SMEM_B);
    nkm_mma<<<nb, TPB, SMEM_B>>>(X, C, out, N);
}